// round 12
// baseline (speedup 1.0000x reference)
#include <cuda_runtime.h>
#include <math.h>
#include <stdint.h>

#define Bb 64
#define Ss 1024
#define Ee 300
#define Hh 256
#define Gg 1024
#define DHh 512
#define DAa 64
#define Rr 16
#define MHh 512
#define RKk 8192

#define ET_OFF   0
#define PRT_OFF  3200
#define POPT_OFF 3968
#define H_OFF    4480
#define C_OFF    37248
#define PEN_OFF  70016
#define A_OFF    70017

__device__ float g_xw_f[Bb * Ss * Gg];
__device__ float g_xw_b[Bb * Ss * Gg];
__device__ float g_S1t[DHh * DAa];
__device__ float g_Hout[Bb * Ss * DHh];
__device__ float g_s2[Bb * Rr * Ss];   // [b][r][t]
__device__ float g_BM[Bb * RKk];
__device__ float g_hid[3 * Bb * MHh];
__device__ float g_pp[Bb];

__device__ __forceinline__ float sigf(float x) {
    return 1.f / (1.f + expf(-x));
}
__device__ __forceinline__ void ffma2(unsigned long long& d, unsigned long long a,
                                      unsigned long long b) {
    asm("fma.rn.f32x2 %0, %1, %2, %0;" : "+l"(d) : "l"(a), "l"(b));
}
__device__ __forceinline__ float hadd2(unsigned long long v) {
    union { unsigned long long u; float2 f; } cv;
    cv.u = v;
    return cv.f.x + cv.f.y;
}
__device__ __forceinline__ uint32_t smem_u32(const void* p) {
    return (uint32_t)__cvta_generic_to_shared(p);
}
__device__ __forceinline__ uint32_t mapa_u32(uint32_t a, uint32_t r) {
    uint32_t o;
    asm("mapa.shared::cluster.u32 %0, %1, %2;" : "=r"(o) : "r"(a), "r"(r));
    return o;
}
__device__ __forceinline__ void stc_f32(uint32_t a, float v) {
    asm volatile("st.shared::cluster.f32 [%0], %1;" :: "r"(a), "f"(v) : "memory");
}
#define CLUSTER_ARRIVE() asm volatile("barrier.cluster.arrive.aligned;" ::: "memory")
#define CLUSTER_WAIT()   asm volatile("barrier.cluster.wait.aligned;" ::: "memory")
#define CLUSTER_SYNC() do { CLUSTER_ARRIVE(); CLUSTER_WAIT(); } while (0)

// ---- S1 transpose only (64x512 -> 512x64)
__global__ void k_transpose(const float* __restrict__ S1) {
    int c0 = blockIdx.x * 32, r0 = blockIdx.y * 32;
    __shared__ float tile[32][33];
    int tx = threadIdx.x, ty = threadIdx.y;
#pragma unroll
    for (int i = 0; i < 4; i++)
        tile[ty + i * 8][tx] = S1[(size_t)(r0 + ty + i * 8) * DHh + c0 + tx];
    __syncthreads();
#pragma unroll
    for (int i = 0; i < 4; i++)
        g_S1t[(size_t)(c0 + ty + i * 8) * DAa + r0 + tx] = tile[tx][ty + i * 8];
}

// ---- xw = emb[ids] @ W_ih^T (M=65536, N=1024, K=300), both dirs; skip masked tiles
__global__ void __launch_bounds__(256) k_gemm_xw(const int* __restrict__ ids,
                                                 const float* __restrict__ emb,
                                                 const float* __restrict__ Wf,
                                                 const float* __restrict__ Wb,
                                                 const int* __restrict__ len_li) {
    int m0 = blockIdx.y * 128, n0 = blockIdx.x * 128;
    {
        int b = m0 >> 10, t0 = m0 & 1023;
        if (t0 >= len_li[b]) return;
    }
    const float* Wp = blockIdx.z ? Wb : Wf;
    float* out = blockIdx.z ? g_xw_b : g_xw_f;
    __shared__ __align__(16) float As2[8][256];   // duplicated: [kk][2m],[2m+1]
    __shared__ __align__(16) float Bs[8][128];
    __shared__ int roff[128];
    int tid = threadIdx.x;
    if (tid < 128) roff[tid] = ids[m0 + tid] * Ee;

    unsigned long long acc2[8][4];
#pragma unroll
    for (int i = 0; i < 8; i++)
#pragma unroll
        for (int j = 0; j < 4; j++) acc2[i][j] = 0ULL;

    int mloc = tid >> 1;
    int kloc = (tid & 1) * 4;
    int ty = tid >> 4, tx = tid & 15;
    __syncthreads();

    for (int k0 = 0; k0 < Ee; k0 += 8) {
#pragma unroll
        for (int i = 0; i < 4; i++) {
            int kk = kloc + i, kg = k0 + kk;
            float av = (kg < Ee) ? emb[(size_t)roff[mloc] + kg] : 0.f;
            As2[kk][2 * mloc] = av;
            As2[kk][2 * mloc + 1] = av;
            Bs[kk][mloc] = (kg < Ee) ? Wp[(size_t)(n0 + mloc) * Ee + kg] : 0.f;
        }
        __syncthreads();
#pragma unroll
        for (int kk = 0; kk < 8; kk++) {
            unsigned long long bp[4];
            const unsigned long long* bsrc = (const unsigned long long*)&Bs[kk][tx * 8];
            bp[0] = bsrc[0]; bp[1] = bsrc[1]; bp[2] = bsrc[2]; bp[3] = bsrc[3];
#pragma unroll
            for (int i = 0; i < 8; i++) {
                unsigned long long ad =
                    *(const unsigned long long*)&As2[kk][2 * (ty * 8 + i)];
                ffma2(acc2[i][0], ad, bp[0]);
                ffma2(acc2[i][1], ad, bp[1]);
                ffma2(acc2[i][2], ad, bp[2]);
                ffma2(acc2[i][3], ad, bp[3]);
            }
        }
        __syncthreads();
    }
#pragma unroll
    for (int i = 0; i < 8; i++) {
        float* orow = out + (size_t)(m0 + ty * 8 + i) * Gg + n0 + tx * 8;
        ((ulonglong2*)orow)[0] = make_ulonglong2(acc2[i][0], acc2[i][1]);
        ((ulonglong2*)orow)[1] = make_ulonglong2(acc2[i][2], acc2[i][3]);
    }
}

// ---- LSTM recurrence: cluster of 8 CTAs per 8 batches, W slice resident in smem.
// grid (64, 2), cluster (8,1,1), 256 threads.
// smem: Wv4 [64 pp][128 cc] float4 (128KB) | hbuf [2][8][256] (16KB) | sg [128][9]
#define LSTM_SMEM_FLOATS (32768 + 4096 + 1152)
__global__ void __launch_bounds__(256, 1) __cluster_dims__(8, 1, 1)
k_lstm(const float* __restrict__ Whf, const float* __restrict__ Whb,
       const float* __restrict__ h0, const float* __restrict__ c0,
       const int* __restrict__ len_li, float* __restrict__ dout) {
    extern __shared__ float smem[];
    float4* Wv = (float4*)smem;              // [pp*128 + cc]
    float* hb = smem + 32768;                // [buf*2048 + b*256 + j]
    float* sg = smem + 32768 + 4096;         // [cc*9 + b]
    __shared__ int slen[8];

    int tid = threadIdx.x;
    int dir = blockIdx.y;
    int rank = blockIdx.x & 7;
    int b0 = (blockIdx.x >> 3) * 8;
    int j0 = rank * 32;
    const float* Whh = dir ? Whb : Whf;
    const float* xw  = dir ? g_xw_b : g_xw_f;

    // load W rows for this CTA's 128 gate columns
    for (int i = tid; i < 128 * 64; i += 256) {
        int cc = i >> 6, pp = i & 63;
        int gcol = (cc >> 5) * 256 + j0 + (cc & 31);
        Wv[pp * 128 + cc] = *(const float4*)&Whh[(size_t)gcol * Hh + pp * 4];
    }
    // load full h0 for 8 batches into buffer 0
    for (int i = tid; i < 8 * Hh; i += 256)
        hb[i] = h0[(size_t)(dir * Bb + b0) * Hh + i];
    if (tid < 8) slen[tid] = len_li[b0 + tid];
    __syncthreads();

    int maxlen = 0;
#pragma unroll
    for (int i = 0; i < 8; i++) maxlen = max(maxlen, slen[i]);

    // phase-B persistent state: thread -> (batch pb, dim j0+pj)
    int pb = tid >> 5, pj = tid & 31;
    int plen = slen[pb];
    float creg = c0[(size_t)(dir * Bb + b0 + pb) * Hh + j0 + pj];
    float hreg = hb[pb * Hh + j0 + pj];

    // phase-A mapping: thread -> (batch group g, column cc)
    int g = tid >> 7;            // 0/1 -> batches 4g..4g+3
    int cc = tid & 127;
    int gcol = (cc >> 5) * 256 + j0 + (cc & 31);
    int alen[4];
#pragma unroll
    for (int m = 0; m < 4; m++) alen[m] = slen[4 * g + m];
    const ulonglong2* wcol2 = (const ulonglong2*)Wv + cc;
    const float* xwb = xw + ((size_t)(b0 + 4 * g) * Ss) * Gg + gcol;

    // DSMEM peer addresses of hb
    uint32_t hb_u = smem_u32(hb);
    uint32_t peer[8];
#pragma unroll
    for (int r = 0; r < 8; r++) peer[r] = mapa_u32(hb_u, (uint32_t)r);

    CLUSTER_SYNC();

    // prologue xv for t=0
    float xv[4];
#pragma unroll
    for (int m = 0; m < 4; m++) {
        int pos = dir ? alen[m] - 1 : 0;
        if (pos < 0) pos = 0;
        xv[m] = __ldg(xwb + ((size_t)m * Ss + pos) * Gg);
    }

    int cur = 0;
    for (int t = 0; t < maxlen; t++) {
        // dot: gates[4 batches][my col] over k=256, packed f32x2, zero-MOV
        unsigned long long acc[4] = {0ULL, 0ULL, 0ULL, 0ULL};
        const float* hc = hb + cur * 2048 + g * 4 * Hh;
#pragma unroll 16
        for (int pp = 0; pp < 64; pp++) {
            ulonglong2 w = wcol2[pp * 128];
            ulonglong2 h0v = *(const ulonglong2*)&hc[0 * Hh + pp * 4];
            ulonglong2 h1v = *(const ulonglong2*)&hc[1 * Hh + pp * 4];
            ulonglong2 h2v = *(const ulonglong2*)&hc[2 * Hh + pp * 4];
            ulonglong2 h3v = *(const ulonglong2*)&hc[3 * Hh + pp * 4];
            ffma2(acc[0], w.x, h0v.x); ffma2(acc[0], w.y, h0v.y);
            ffma2(acc[1], w.x, h1v.x); ffma2(acc[1], w.y, h1v.y);
            ffma2(acc[2], w.x, h2v.x); ffma2(acc[2], w.y, h2v.y);
            ffma2(acc[3], w.x, h3v.x); ffma2(acc[3], w.y, h3v.y);
        }
#pragma unroll
        for (int m = 0; m < 4; m++)
            sg[cc * 9 + 4 * g + m] = hadd2(acc[m]) + xv[m];
        __syncthreads();

        // nonlinearity + state update for (pb, j0+pj), then DSMEM broadcast
        float gi = sg[(pj) * 9 + pb];
        float gf = sg[(32 + pj) * 9 + pb];
        float gg = sg[(64 + pj) * 9 + pb];
        float go = sg[(96 + pj) * 9 + pb];
        if (t < plen) {
            creg = sigf(gf) * creg + sigf(gi) * tanhf(gg);
            hreg = sigf(go) * tanhf(creg);
        }
        uint32_t off = (uint32_t)(((cur ^ 1) * 2048 + pb * Hh + j0 + pj) * 4);
#pragma unroll
        for (int r = 0; r < 8; r++) stc_f32(peer[r] + off, hreg);

        CLUSTER_ARRIVE();

        // overlap with barrier: Hout store + next-step xv prefetch
        if (t < plen) {
            int pos = dir ? plen - 1 - t : t;
            g_Hout[((size_t)(b0 + pb) * Ss + pos) * DHh + dir * Hh + j0 + pj] = hreg;
        }
        if (t + 1 < maxlen) {
#pragma unroll
            for (int m = 0; m < 4; m++) {
                int pos = dir ? alen[m] - 2 - t : t + 1;
                if (pos < 0) pos = 0;
                xv[m] = __ldg(xwb + ((size_t)m * Ss + pos) * Gg);
            }
        }

        CLUSTER_WAIT();
        cur ^= 1;
    }
    dout[H_OFF + (size_t)(dir * Bb + b0 + pb) * Hh + j0 + pj] = hreg;
    dout[C_OFF + (size_t)(dir * Bb + b0 + pb) * Hh + j0 + pj] = creg;
}

// ---- s2 = tanh(Hout @ S1^T) @ S2^T, write [b][r][t]; skip masked tiles
__global__ void __launch_bounds__(256) k_s2(const float* __restrict__ S2,
                                            const int* __restrict__ len_li) {
    size_t row0 = (size_t)blockIdx.x * 16;
    int b = (int)(row0 >> 10);
    int t0 = (int)(row0 & 1023);
    if (t0 >= len_li[b]) return;

    __shared__ __align__(16) float Hs[16][DHh];
    __shared__ float t1[16][DAa];
    __shared__ float so[16][17];
    int tid = threadIdx.x;
    for (int idx = tid; idx < 16 * DHh / 4; idx += 256) {
        int r = idx / (DHh / 4);
        int c4 = (idx % (DHh / 4)) * 4;
        *(float4*)&Hs[r][c4] = *(const float4*)&g_Hout[(row0 + r) * DHh + c4];
    }
    __syncthreads();

    int da = tid & 63;
    int rl = tid >> 6;
    float acc[4] = {0.f, 0.f, 0.f, 0.f};
    for (int k = 0; k < DHh; k++) {
        float w = g_S1t[(size_t)k * DAa + da];
        acc[0] = fmaf(w, Hs[rl + 0][k], acc[0]);
        acc[1] = fmaf(w, Hs[rl + 4][k], acc[1]);
        acc[2] = fmaf(w, Hs[rl + 8][k], acc[2]);
        acc[3] = fmaf(w, Hs[rl + 12][k], acc[3]);
    }
    t1[rl + 0][da]  = tanhf(acc[0]);
    t1[rl + 4][da]  = tanhf(acc[1]);
    t1[rl + 8][da]  = tanhf(acc[2]);
    t1[rl + 12][da] = tanhf(acc[3]);
    __syncthreads();

    int row = tid >> 4, rh = tid & 15;
    float s = 0.f;
#pragma unroll 8
    for (int k = 0; k < DAa; k++) s = fmaf(t1[row][k], __ldg(&S2[rh * DAa + k]), s);
    so[row][rh] = s;
    __syncthreads();
    int rr = tid >> 4, tt = tid & 15;
    g_s2[((size_t)b * Rr + rr) * Ss + t0 + tt] = so[tt][rr];
}

// ---- masked softmax over t; A written to dout. grid (R, B)
__global__ void __launch_bounds__(256) k_softmax(const int* __restrict__ len_li,
                                                 float* __restrict__ dout) {
    int r = blockIdx.x, b = blockIdx.y;
    int len = len_li[b];
    int tid = threadIdx.x;
    __shared__ float red[256];
    const float* srow = g_s2 + ((size_t)b * Rr + r) * Ss;
    float* Aout = dout + A_OFF + ((size_t)b * Rr + r) * Ss;

    float m = -1e30f;
    for (int t = tid; t < len; t += 256) m = fmaxf(m, srow[t]);
    red[tid] = m; __syncthreads();
    for (int s = 128; s > 0; s >>= 1) {
        if (tid < s) red[tid] = fmaxf(red[tid], red[tid + s]);
        __syncthreads();
    }
    float M = red[0]; __syncthreads();

    float sum = 0.f;
    for (int t = tid; t < len; t += 256) {
        float e = expf(srow[t] - M);
        Aout[t] = e;
        sum += e;
    }
    red[tid] = sum; __syncthreads();
    for (int s = 128; s > 0; s >>= 1) {
        if (tid < s) red[tid] += red[tid + s];
        __syncthreads();
    }
    float inv = 1.f / red[0];

    for (int t = tid; t < Ss; t += 256)
        Aout[t] = (t < len) ? Aout[t] * inv : 0.f;
}

// ---- BM = A @ Hout. block per b, 512 thr (d)
__global__ void __launch_bounds__(512) k_M(const int* __restrict__ len_li,
                                           const float* __restrict__ dout) {
    int b = blockIdx.x;
    int tid = threadIdx.x;
    int len = len_li[b];
    __shared__ __align__(16) float Asm[128][16];
    float acc[16];
#pragma unroll
    for (int i = 0; i < 16; i++) acc[i] = 0.f;

    const float* Abase = dout + A_OFF + (size_t)b * Rr * Ss;
    for (int tc = 0; tc < len; tc += 128) {
        int nt = min(128, len - tc);
        for (int idx = tid; idx < 16 * 128; idx += 512) {
            int r = idx >> 7, tt = idx & 127;
            Asm[tt][r] = (tt < nt) ? Abase[(size_t)r * Ss + tc + tt] : 0.f;
        }
        __syncthreads();
        for (int tt = 0; tt < nt; tt++) {
            float hv = g_Hout[((size_t)b * Ss + tc + tt) * DHh + tid];
#pragma unroll
            for (int r2 = 0; r2 < 16; r2++)
                acc[r2] = fmaf(Asm[tt][r2], hv, acc[r2]);
        }
        __syncthreads();
    }
#pragma unroll
    for (int r2 = 0; r2 < 16; r2++)
        g_BM[(size_t)b * RKk + r2 * DHh + tid] = acc[r2];
}

// ---- AAT penal partial. block per b, thread (r,q)
__global__ void __launch_bounds__(256) k_aat(const int* __restrict__ len_li,
                                             const float* __restrict__ dout) {
    int b = blockIdx.x;
    int tid = threadIdx.x;
    int r = tid >> 4, q = tid & 15;
    int len = len_li[b];
    const float* Abase = dout + A_OFF + (size_t)b * Rr * Ss;
    __shared__ float As2[16][257];
    float s = 0.f;
    for (int tc = 0; tc < len; tc += 256) {
        int nt = min(256, len - tc);
        for (int i = tid; i < 16 * 256; i += 256) {
            int rr = i >> 8, tt = i & 255;
            As2[rr][tt] = (tt < nt) ? Abase[(size_t)rr * Ss + tc + tt] : 0.f;
        }
        __syncthreads();
#pragma unroll 4
        for (int tt = 0; tt < 256; tt++)
            s = fmaf(As2[r][tt], As2[q][tt], s);
        __syncthreads();
    }
    float d = s - (r == q ? 1.f : 0.f);
    __shared__ float red[256];
    red[tid] = d * d; __syncthreads();
    for (int st = 128; st > 0; st >>= 1) {
        if (tid < st) red[tid] += red[tid + st];
        __syncthreads();
    }
    if (tid == 0) g_pp[b] = red[0];
}

__global__ void k_pen(float* __restrict__ dout) {
    __shared__ float red[64];
    int tid = threadIdx.x;
    red[tid] = g_pp[tid]; __syncthreads();
    for (int st = 32; st > 0; st >>= 1) {
        if (tid < st) red[tid] += red[tid + st];
        __syncthreads();
    }
    if (tid == 0) dout[PEN_OFF] = red[0] / 64.f;
}

// ---- hid = relu(BM @ W^T + b): tiled GEMM, 96 blocks
__global__ void __launch_bounds__(256) k_hid(const float* __restrict__ Wet,  const float* __restrict__ bet,
                                             const float* __restrict__ Wprt, const float* __restrict__ bprt,
                                             const float* __restrict__ Wpop, const float* __restrict__ bpop) {
    int blk = blockIdx.x;
    int head = blk >> 5;
    int j0 = (blk & 31) * 16;
    const float* W    = (head == 0) ? Wet : (head == 1) ? Wprt : Wpop;
    const float* bias = (head == 0) ? bet : (head == 1) ? bprt : bpop;
    __shared__ float Ws[16][64];
    __shared__ float Bs[64][65];
    int tid = threadIdx.x;
    int rj = tid >> 4;
    int bq = (tid & 15) * 4;
    float acc[4] = {0.f, 0.f, 0.f, 0.f};
    for (int kc = 0; kc < RKk; kc += 64) {
        for (int i = tid; i < 1024; i += 256) {
            int r = i >> 6, k = i & 63;
            Ws[r][k] = W[(size_t)(j0 + r) * RKk + kc + k];
        }
        for (int i = tid; i < 4096; i += 256) {
            int bx = i >> 6, k = i & 63;
            Bs[bx][k] = g_BM[(size_t)bx * RKk + kc + k];
        }
        __syncthreads();
#pragma unroll 4
        for (int k = 0; k < 64; k++) {
            float w = Ws[rj][k];
            acc[0] = fmaf(w, Bs[bq + 0][k], acc[0]);
            acc[1] = fmaf(w, Bs[bq + 1][k], acc[1]);
            acc[2] = fmaf(w, Bs[bq + 2][k], acc[2]);
            acc[3] = fmaf(w, Bs[bq + 3][k], acc[3]);
        }
        __syncthreads();
    }
    float bv = bias[j0 + rj];
#pragma unroll
    for (int q = 0; q < 4; q++)
        g_hid[((size_t)head * Bb + bq + q) * MHh + j0 + rj] = fmaxf(acc[q] + bv, 0.f);
}

// ---- decode: grid (B, 3), 64 threads
__global__ void __launch_bounds__(64) k_dec(const float* __restrict__ Wdet,  const float* __restrict__ bdet,
                                            const float* __restrict__ Wdprt, const float* __restrict__ bdprt,
                                            const float* __restrict__ Wdpop, const float* __restrict__ bdpop,
                                            float* __restrict__ dout) {
    int b = blockIdx.x, head = blockIdx.y;
    int tid = threadIdx.x;
    const float* Wd; const float* bd; int N; int off;
    if (head == 0)      { Wd = Wdet;  bd = bdet;  N = 50; off = ET_OFF;   }
    else if (head == 1) { Wd = Wdprt; bd = bdprt; N = 12; off = PRT_OFF;  }
    else                { Wd = Wdpop; bd = bdpop; N = 8;  off = POPT_OFF; }
    __shared__ float sh[MHh];
    for (int k = tid; k < MHh; k += 64)
        sh[k] = g_hid[((size_t)head * Bb + b) * MHh + k];
    __syncthreads();
    if (tid < N) {
        float s = bd[tid];
        const float* wr = Wd + (size_t)tid * MHh;
        for (int k = 0; k < MHh; k++) s = fmaf(sh[k], wr[k], s);
        dout[off + b * N + tid] = s;
    }
}

extern "C" void kernel_launch(void* const* d_in, const int* in_sizes, int n_in,
                              void* d_out, int out_size) {
    const int*   ids   = (const int*)d_in[0];
    const int*   lens  = (const int*)d_in[1];
    const float* h0    = (const float*)d_in[2];
    const float* c0    = (const float*)d_in[3];
    const float* emb   = (const float*)d_in[4];
    const float* Wihf  = (const float*)d_in[5];
    const float* Whhf  = (const float*)d_in[6];
    const float* Wihb  = (const float*)d_in[7];
    const float* Whhb  = (const float*)d_in[8];
    const float* S1    = (const float*)d_in[9];
    const float* S2    = (const float*)d_in[10];
    const float* Wet   = (const float*)d_in[11];
    const float* bet   = (const float*)d_in[12];
    const float* Wdet  = (const float*)d_in[13];
    const float* bdet  = (const float*)d_in[14];
    const float* Wprt  = (const float*)d_in[15];
    const float* bprt  = (const float*)d_in[16];
    const float* Wdprt = (const float*)d_in[17];
    const float* bdprt = (const float*)d_in[18];
    const float* Wpop  = (const float*)d_in[19];
    const float* bpop  = (const float*)d_in[20];
    const float* Wdpop = (const float*)d_in[21];
    const float* bdpop = (const float*)d_in[22];
    float* dout = (float*)d_out;

    static int smem_set = 0;
    if (!smem_set) {
        cudaFuncSetAttribute(k_lstm, cudaFuncAttributeMaxDynamicSharedMemorySize,
                             LSTM_SMEM_FLOATS * 4);
        smem_set = 1;
    }

    k_transpose<<<dim3(16, 2), dim3(32, 8)>>>(S1);
    k_gemm_xw<<<dim3(8, 512, 2), 256>>>(ids, emb, Wihf, Wihb, lens);
    k_lstm<<<dim3(64, 2), 256, LSTM_SMEM_FLOATS * 4>>>(Whhf, Whhb, h0, c0, lens, dout);
    k_s2<<<4096, 256>>>(S2, lens);
    k_softmax<<<dim3(Rr, Bb), 256>>>(lens, dout);
    k_M<<<Bb, 512>>>(lens, dout);
    k_aat<<<Bb, 256>>>(lens, dout);
    k_pen<<<1, 64>>>(dout);
    k_hid<<<96, 256>>>(Wet, bet, Wprt, bprt, Wpop, bpop);
    k_dec<<<dim3(Bb, 3), 64>>>(Wdet, bdet, Wdprt, bdprt, Wdpop, bdpop, dout);
}

// round 13
// speedup vs baseline: 1.1526x; 1.1526x over previous
#include <cuda_runtime.h>
#include <math.h>
#include <stdint.h>

#define Bb 64
#define Ss 1024
#define Ee 300
#define Hh 256
#define Gg 1024
#define DHh 512
#define DAa 64
#define Rr 16
#define MHh 512
#define RKk 8192

#define ET_OFF   0
#define PRT_OFF  3200
#define POPT_OFF 3968
#define H_OFF    4480
#define C_OFF    37248
#define PEN_OFF  70016
#define A_OFF    70017

__device__ float g_xw_f[Bb * Ss * Gg];
__device__ float g_xw_b[Bb * Ss * Gg];
__device__ float g_S1t[DHh * DAa];
__device__ float g_Hout[Bb * Ss * DHh];
__device__ float g_s2[Bb * Rr * Ss];   // [b][r][t]
__device__ float g_BM[Bb * RKk];
__device__ float g_hid[3 * Bb * MHh];
__device__ float g_pp[Bb];

__device__ __forceinline__ float sigf(float x) {
    return 1.f / (1.f + expf(-x));
}
__device__ __forceinline__ void ffma2(unsigned long long& d, unsigned long long a,
                                      unsigned long long b) {
    asm("fma.rn.f32x2 %0, %1, %2, %0;" : "+l"(d) : "l"(a), "l"(b));
}
__device__ __forceinline__ unsigned long long pack2(float x, float y) {
    unsigned long long r;
    asm("mov.b64 %0, {%1, %2};" : "=l"(r) : "r"(__float_as_uint(x)), "r"(__float_as_uint(y)));
    return r;
}
__device__ __forceinline__ float hadd2(unsigned long long v) {
    union { unsigned long long u; float2 f; } cv;
    cv.u = v;
    return cv.f.x + cv.f.y;
}
__device__ __forceinline__ uint32_t smem_u32(const void* p) {
    return (uint32_t)__cvta_generic_to_shared(p);
}
__device__ __forceinline__ uint32_t mapa_u32(uint32_t a, uint32_t r) {
    uint32_t o;
    asm("mapa.shared::cluster.u32 %0, %1, %2;" : "=r"(o) : "r"(a), "r"(r));
    return o;
}
__device__ __forceinline__ void stc_f32(uint32_t a, float v) {
    asm volatile("st.shared::cluster.f32 [%0], %1;" :: "r"(a), "f"(v) : "memory");
}
#define CLUSTER_SYNC() do { \
    asm volatile("barrier.cluster.arrive.aligned;" ::: "memory"); \
    asm volatile("barrier.cluster.wait.aligned;" ::: "memory"); \
} while (0)

// ---- S1 transpose only (64x512 -> 512x64)
__global__ void k_transpose(const float* __restrict__ S1) {
    int c0 = blockIdx.x * 32, r0 = blockIdx.y * 32;
    __shared__ float tile[32][33];
    int tx = threadIdx.x, ty = threadIdx.y;
#pragma unroll
    for (int i = 0; i < 4; i++)
        tile[ty + i * 8][tx] = S1[(size_t)(r0 + ty + i * 8) * DHh + c0 + tx];
    __syncthreads();
#pragma unroll
    for (int i = 0; i < 4; i++)
        g_S1t[(size_t)(c0 + ty + i * 8) * DAa + r0 + tx] = tile[tx][ty + i * 8];
}

// ---- xw = emb[ids] @ W_ih^T (M=65536, N=1024, K=300), both dirs; skip masked tiles
__global__ void __launch_bounds__(256) k_gemm_xw(const int* __restrict__ ids,
                                                 const float* __restrict__ emb,
                                                 const float* __restrict__ Wf,
                                                 const float* __restrict__ Wb,
                                                 const int* __restrict__ len_li) {
    int m0 = blockIdx.y * 128, n0 = blockIdx.x * 128;
    {
        int b = m0 >> 10, t0 = m0 & 1023;
        if (t0 >= len_li[b]) return;
    }
    const float* Wp = blockIdx.z ? Wb : Wf;
    float* out = blockIdx.z ? g_xw_b : g_xw_f;
    __shared__ __align__(16) float As[8][128];
    __shared__ __align__(16) float Bs[8][128];
    __shared__ int roff[128];
    int tid = threadIdx.x;
    if (tid < 128) roff[tid] = ids[m0 + tid] * Ee;

    unsigned long long acc2[8][4];
#pragma unroll
    for (int i = 0; i < 8; i++)
#pragma unroll
        for (int j = 0; j < 4; j++) acc2[i][j] = 0ULL;

    int mloc = tid >> 1;
    int kloc = (tid & 1) * 4;
    int ty = tid >> 4, tx = tid & 15;
    __syncthreads();

    for (int k0 = 0; k0 < Ee; k0 += 8) {
#pragma unroll
        for (int i = 0; i < 4; i++) {
            int kk = kloc + i, kg = k0 + kk;
            As[kk][mloc] = (kg < Ee) ? emb[(size_t)roff[mloc] + kg] : 0.f;
            Bs[kk][mloc] = (kg < Ee) ? Wp[(size_t)(n0 + mloc) * Ee + kg] : 0.f;
        }
        __syncthreads();
#pragma unroll
        for (int kk = 0; kk < 8; kk++) {
            float a[8];
            *(float4*)&a[0] = *(float4*)&As[kk][ty * 8];
            *(float4*)&a[4] = *(float4*)&As[kk][ty * 8 + 4];
            unsigned long long bp[4];
            const unsigned long long* bsrc = (const unsigned long long*)&Bs[kk][tx * 8];
            bp[0] = bsrc[0]; bp[1] = bsrc[1]; bp[2] = bsrc[2]; bp[3] = bsrc[3];
#pragma unroll
            for (int i = 0; i < 8; i++) {
                unsigned long long ad = pack2(a[i], a[i]);
                ffma2(acc2[i][0], ad, bp[0]);
                ffma2(acc2[i][1], ad, bp[1]);
                ffma2(acc2[i][2], ad, bp[2]);
                ffma2(acc2[i][3], ad, bp[3]);
            }
        }
        __syncthreads();
    }
#pragma unroll
    for (int i = 0; i < 8; i++) {
        float* orow = out + (size_t)(m0 + ty * 8 + i) * Gg + n0 + tx * 8;
        ((ulonglong2*)orow)[0] = make_ulonglong2(acc2[i][0], acc2[i][1]);
        ((ulonglong2*)orow)[1] = make_ulonglong2(acc2[i][2], acc2[i][3]);
    }
}

// ---- LSTM recurrence: cluster of 8 CTAs per 8 batches, W slice resident in smem.
// grid (64, 2), cluster (8,1,1), 512 threads.
// Phase A: thread = (kh in 0..3 k-quarter, cc in 0..127 gate col), 8 batches/thread.
// W read exactly once per step; 16 warps for latency hiding.
// smem: Wv4 [64 pp][128 cc] float4 (128KB) | hbuf [2][8][256] (16KB) | sg [128][37]
#define LSTM_SMEM_FLOATS (32768 + 4096 + 4736)
__global__ void __launch_bounds__(512, 1) __cluster_dims__(8, 1, 1)
k_lstm(const float* __restrict__ Whf, const float* __restrict__ Whb,
       const float* __restrict__ h0, const float* __restrict__ c0,
       const int* __restrict__ len_li, float* __restrict__ dout) {
    extern __shared__ float smem[];
    float4* Wv = (float4*)smem;              // [pp*128 + cc]
    float* hb = smem + 32768;                // [buf*2048 + b*256 + j]
    float* sg = smem + 32768 + 4096;         // [cc*37 + kh*9 + m]
    __shared__ int slen[8];

    int tid = threadIdx.x;
    int dir = blockIdx.y;
    int rank = blockIdx.x & 7;
    int b0 = (blockIdx.x >> 3) * 8;
    int j0 = rank * 32;
    const float* Whh = dir ? Whb : Whf;
    const float* xw  = dir ? g_xw_b : g_xw_f;

    // load W rows for this CTA's 128 gate columns
    for (int i = tid; i < 128 * 64; i += 512) {
        int cc = i >> 6, pp = i & 63;
        int gcol = (cc >> 5) * 256 + j0 + (cc & 31);
        Wv[pp * 128 + cc] = *(const float4*)&Whh[(size_t)gcol * Hh + pp * 4];
    }
    // load full h0 for 8 batches into buffer 0
    for (int i = tid; i < 8 * Hh; i += 512)
        hb[i] = h0[(size_t)(dir * Bb + b0) * Hh + i];
    if (tid < 8) slen[tid] = len_li[b0 + tid];
    __syncthreads();

    int maxlen = 0;
#pragma unroll
    for (int i = 0; i < 8; i++) maxlen = max(maxlen, slen[i]);

    // phase-B persistent state: first 256 threads -> (batch pb, dim j0+pj)
    bool active = tid < 256;
    int pb = (tid >> 5) & 7, pj = tid & 31;
    int plen = slen[pb];
    float creg = active ? c0[(size_t)(dir * Bb + b0 + pb) * Hh + j0 + pj] : 0.f;
    float hreg = active ? hb[pb * Hh + j0 + pj] : 0.f;

    // phase-A mapping: thread -> (k-quarter kh, column cc)
    int kh = tid >> 7;           // 0..3
    int cc = tid & 127;
    int gcol = (cc >> 5) * 256 + j0 + (cc & 31);
    int ppbase = kh * 16;
    // this thread owns xw for batches mA=2kh, mB=2kh+1
    int mA = kh * 2, mB = kh * 2 + 1;
    int lenA = slen[mA], lenB = slen[mB];
    const float* xwA = xw + ((size_t)(b0 + mA) * Ss) * Gg + gcol;
    const float* xwB = xw + ((size_t)(b0 + mB) * Ss) * Gg + gcol;
    const ulonglong2* wcol2 = (const ulonglong2*)Wv + cc;

    // DSMEM peer addresses of hb
    uint32_t hb_u = smem_u32(hb);
    uint32_t peer[8];
#pragma unroll
    for (int r = 0; r < 8; r++) peer[r] = mapa_u32(hb_u, (uint32_t)r);

    CLUSTER_SYNC();

    int cur = 0;
    for (int t = 0; t < maxlen; t++) {
        // xv loads for this thread's 2 owned batches
        int posA = dir ? lenA - 1 - t : t; if (posA < 0) posA = 0;
        int posB = dir ? lenB - 1 - t : t; if (posB < 0) posB = 0;
        float xvA = __ldg(xwA + (size_t)posA * Gg);
        float xvB = __ldg(xwB + (size_t)posB * Gg);

        // partial dot over this thread's 16 k-pairs, all 8 batches
        unsigned long long acc[8] = {0ULL,0ULL,0ULL,0ULL,0ULL,0ULL,0ULL,0ULL};
        const float* hc = hb + cur * 2048;
#pragma unroll 4
        for (int pp = 0; pp < 16; pp++) {
            ulonglong2 w = wcol2[(ppbase + pp) * 128];
#pragma unroll
            for (int m = 0; m < 8; m++) {
                ulonglong2 hv = *(const ulonglong2*)&hc[m * Hh + (ppbase + pp) * 4];
                ffma2(acc[m], w.x, hv.x);
                ffma2(acc[m], w.y, hv.y);
            }
        }
        float part[8];
#pragma unroll
        for (int m = 0; m < 8; m++) part[m] = hadd2(acc[m]);
        part[mA] += xvA;
        part[mB] += xvB;
#pragma unroll
        for (int m = 0; m < 8; m++)
            sg[cc * 37 + kh * 9 + m] = part[m];
        __syncthreads();

        // phase B: reduce 4 partials, nonlinearity, state update, DSMEM broadcast
        if (active) {
            float gi = sg[(pj) * 37 + pb]       + sg[(pj) * 37 + 9 + pb]
                     + sg[(pj) * 37 + 18 + pb]  + sg[(pj) * 37 + 27 + pb];
            float gf = sg[(32 + pj) * 37 + pb]      + sg[(32 + pj) * 37 + 9 + pb]
                     + sg[(32 + pj) * 37 + 18 + pb] + sg[(32 + pj) * 37 + 27 + pb];
            float gg = sg[(64 + pj) * 37 + pb]      + sg[(64 + pj) * 37 + 9 + pb]
                     + sg[(64 + pj) * 37 + 18 + pb] + sg[(64 + pj) * 37 + 27 + pb];
            float go = sg[(96 + pj) * 37 + pb]      + sg[(96 + pj) * 37 + 9 + pb]
                     + sg[(96 + pj) * 37 + 18 + pb] + sg[(96 + pj) * 37 + 27 + pb];
            if (t < plen) {
                creg = sigf(gf) * creg + sigf(gi) * tanhf(gg);
                hreg = sigf(go) * tanhf(creg);
                int pos = dir ? plen - 1 - t : t;
                g_Hout[((size_t)(b0 + pb) * Ss + pos) * DHh + dir * Hh + j0 + pj] = hreg;
            }
            uint32_t off = (uint32_t)(((cur ^ 1) * 2048 + pb * Hh + j0 + pj) * 4);
#pragma unroll
            for (int r = 0; r < 8; r++) stc_f32(peer[r] + off, hreg);
        }
        CLUSTER_SYNC();
        cur ^= 1;
    }
    if (active) {
        dout[H_OFF + (size_t)(dir * Bb + b0 + pb) * Hh + j0 + pj] = hreg;
        dout[C_OFF + (size_t)(dir * Bb + b0 + pb) * Hh + j0 + pj] = creg;
    }
}

// ---- s2 = tanh(Hout @ S1^T) @ S2^T, write [b][r][t]; skip masked tiles
__global__ void __launch_bounds__(256) k_s2(const float* __restrict__ S2,
                                            const int* __restrict__ len_li) {
    size_t row0 = (size_t)blockIdx.x * 16;
    int b = (int)(row0 >> 10);
    int t0 = (int)(row0 & 1023);
    if (t0 >= len_li[b]) return;

    __shared__ __align__(16) float Hs[16][DHh];
    __shared__ float t1[16][DAa];
    __shared__ float so[16][17];
    int tid = threadIdx.x;
    for (int idx = tid; idx < 16 * DHh / 4; idx += 256) {
        int r = idx / (DHh / 4);
        int c4 = (idx % (DHh / 4)) * 4;
        *(float4*)&Hs[r][c4] = *(const float4*)&g_Hout[(row0 + r) * DHh + c4];
    }
    __syncthreads();

    int da = tid & 63;
    int rl = tid >> 6;
    float acc[4] = {0.f, 0.f, 0.f, 0.f};
    for (int k = 0; k < DHh; k++) {
        float w = g_S1t[(size_t)k * DAa + da];
        acc[0] = fmaf(w, Hs[rl + 0][k], acc[0]);
        acc[1] = fmaf(w, Hs[rl + 4][k], acc[1]);
        acc[2] = fmaf(w, Hs[rl + 8][k], acc[2]);
        acc[3] = fmaf(w, Hs[rl + 12][k], acc[3]);
    }
    t1[rl + 0][da]  = tanhf(acc[0]);
    t1[rl + 4][da]  = tanhf(acc[1]);
    t1[rl + 8][da]  = tanhf(acc[2]);
    t1[rl + 12][da] = tanhf(acc[3]);
    __syncthreads();

    int row = tid >> 4, rh = tid & 15;
    float s = 0.f;
#pragma unroll 8
    for (int k = 0; k < DAa; k++) s = fmaf(t1[row][k], __ldg(&S2[rh * DAa + k]), s);
    so[row][rh] = s;
    __syncthreads();
    int rr = tid >> 4, tt = tid & 15;
    g_s2[((size_t)b * Rr + rr) * Ss + t0 + tt] = so[tt][rr];
}

// ---- masked softmax over t; A written to dout. grid (R, B)
__global__ void __launch_bounds__(256) k_softmax(const int* __restrict__ len_li,
                                                 float* __restrict__ dout) {
    int r = blockIdx.x, b = blockIdx.y;
    int len = len_li[b];
    int tid = threadIdx.x;
    __shared__ float red[256];
    const float* srow = g_s2 + ((size_t)b * Rr + r) * Ss;
    float* Aout = dout + A_OFF + ((size_t)b * Rr + r) * Ss;

    float m = -1e30f;
    for (int t = tid; t < len; t += 256) m = fmaxf(m, srow[t]);
    red[tid] = m; __syncthreads();
    for (int s = 128; s > 0; s >>= 1) {
        if (tid < s) red[tid] = fmaxf(red[tid], red[tid + s]);
        __syncthreads();
    }
    float M = red[0]; __syncthreads();

    float sum = 0.f;
    for (int t = tid; t < len; t += 256) {
        float e = expf(srow[t] - M);
        Aout[t] = e;
        sum += e;
    }
    red[tid] = sum; __syncthreads();
    for (int s = 128; s > 0; s >>= 1) {
        if (tid < s) red[tid] += red[tid + s];
        __syncthreads();
    }
    float inv = 1.f / red[0];

    for (int t = tid; t < Ss; t += 256)
        Aout[t] = (t < len) ? Aout[t] * inv : 0.f;
}

// ---- BM = A @ Hout. block per b, 512 thr (d)
__global__ void __launch_bounds__(512) k_M(const int* __restrict__ len_li,
                                           const float* __restrict__ dout) {
    int b = blockIdx.x;
    int tid = threadIdx.x;
    int len = len_li[b];
    __shared__ __align__(16) float Asm[128][16];
    float acc[16];
#pragma unroll
    for (int i = 0; i < 16; i++) acc[i] = 0.f;

    const float* Abase = dout + A_OFF + (size_t)b * Rr * Ss;
    for (int tc = 0; tc < len; tc += 128) {
        int nt = min(128, len - tc);
        for (int idx = tid; idx < 16 * 128; idx += 512) {
            int r = idx >> 7, tt = idx & 127;
            Asm[tt][r] = (tt < nt) ? Abase[(size_t)r * Ss + tc + tt] : 0.f;
        }
        __syncthreads();
        for (int tt = 0; tt < nt; tt++) {
            float hv = g_Hout[((size_t)b * Ss + tc + tt) * DHh + tid];
#pragma unroll
            for (int r2 = 0; r2 < 16; r2++)
                acc[r2] = fmaf(Asm[tt][r2], hv, acc[r2]);
        }
        __syncthreads();
    }
#pragma unroll
    for (int r2 = 0; r2 < 16; r2++)
        g_BM[(size_t)b * RKk + r2 * DHh + tid] = acc[r2];
}

// ---- AAT penal partial. block per b, thread (r,q)
__global__ void __launch_bounds__(256) k_aat(const int* __restrict__ len_li,
                                             const float* __restrict__ dout) {
    int b = blockIdx.x;
    int tid = threadIdx.x;
    int r = tid >> 4, q = tid & 15;
    int len = len_li[b];
    const float* Abase = dout + A_OFF + (size_t)b * Rr * Ss;
    __shared__ float As2[16][257];
    float s = 0.f;
    for (int tc = 0; tc < len; tc += 256) {
        int nt = min(256, len - tc);
        for (int i = tid; i < 16 * 256; i += 256) {
            int rr = i >> 8, tt = i & 255;
            As2[rr][tt] = (tt < nt) ? Abase[(size_t)rr * Ss + tc + tt] : 0.f;
        }
        __syncthreads();
#pragma unroll 4
        for (int tt = 0; tt < 256; tt++)
            s = fmaf(As2[r][tt], As2[q][tt], s);
        __syncthreads();
    }
    float d = s - (r == q ? 1.f : 0.f);
    __shared__ float red[256];
    red[tid] = d * d; __syncthreads();
    for (int st = 128; st > 0; st >>= 1) {
        if (tid < st) red[tid] += red[tid + st];
        __syncthreads();
    }
    if (tid == 0) g_pp[b] = red[0];
}

__global__ void k_pen(float* __restrict__ dout) {
    __shared__ float red[64];
    int tid = threadIdx.x;
    red[tid] = g_pp[tid]; __syncthreads();
    for (int st = 32; st > 0; st >>= 1) {
        if (tid < st) red[tid] += red[tid + st];
        __syncthreads();
    }
    if (tid == 0) dout[PEN_OFF] = red[0] / 64.f;
}

// ---- hid = relu(BM @ W^T + b): tiled GEMM, 96 blocks
__global__ void __launch_bounds__(256) k_hid(const float* __restrict__ Wet,  const float* __restrict__ bet,
                                             const float* __restrict__ Wprt, const float* __restrict__ bprt,
                                             const float* __restrict__ Wpop, const float* __restrict__ bpop) {
    int blk = blockIdx.x;
    int head = blk >> 5;
    int j0 = (blk & 31) * 16;
    const float* W    = (head == 0) ? Wet : (head == 1) ? Wprt : Wpop;
    const float* bias = (head == 0) ? bet : (head == 1) ? bprt : bpop;
    __shared__ float Ws[16][64];
    __shared__ float Bs[64][65];
    int tid = threadIdx.x;
    int rj = tid >> 4;
    int bq = (tid & 15) * 4;
    float acc[4] = {0.f, 0.f, 0.f, 0.f};
    for (int kc = 0; kc < RKk; kc += 64) {
        for (int i = tid; i < 1024; i += 256) {
            int r = i >> 6, k = i & 63;
            Ws[r][k] = W[(size_t)(j0 + r) * RKk + kc + k];
        }
        for (int i = tid; i < 4096; i += 256) {
            int bx = i >> 6, k = i & 63;
            Bs[bx][k] = g_BM[(size_t)bx * RKk + kc + k];
        }
        __syncthreads();
#pragma unroll 4
        for (int k = 0; k < 64; k++) {
            float w = Ws[rj][k];
            acc[0] = fmaf(w, Bs[bq + 0][k], acc[0]);
            acc[1] = fmaf(w, Bs[bq + 1][k], acc[1]);
            acc[2] = fmaf(w, Bs[bq + 2][k], acc[2]);
            acc[3] = fmaf(w, Bs[bq + 3][k], acc[3]);
        }
        __syncthreads();
    }
    float bv = bias[j0 + rj];
#pragma unroll
    for (int q = 0; q < 4; q++)
        g_hid[((size_t)head * Bb + bq + q) * MHh + j0 + rj] = fmaxf(acc[q] + bv, 0.f);
}

// ---- decode: grid (B, 3), 64 threads
__global__ void __launch_bounds__(64) k_dec(const float* __restrict__ Wdet,  const float* __restrict__ bdet,
                                            const float* __restrict__ Wdprt, const float* __restrict__ bdprt,
                                            const float* __restrict__ Wdpop, const float* __restrict__ bdpop,
                                            float* __restrict__ dout) {
    int b = blockIdx.x, head = blockIdx.y;
    int tid = threadIdx.x;
    const float* Wd; const float* bd; int N; int off;
    if (head == 0)      { Wd = Wdet;  bd = bdet;  N = 50; off = ET_OFF;   }
    else if (head == 1) { Wd = Wdprt; bd = bdprt; N = 12; off = PRT_OFF;  }
    else                { Wd = Wdpop; bd = bdpop; N = 8;  off = POPT_OFF; }
    __shared__ float sh[MHh];
    for (int k = tid; k < MHh; k += 64)
        sh[k] = g_hid[((size_t)head * Bb + b) * MHh + k];
    __syncthreads();
    if (tid < N) {
        float s = bd[tid];
        const float* wr = Wd + (size_t)tid * MHh;
        for (int k = 0; k < MHh; k++) s = fmaf(sh[k], wr[k], s);
        dout[off + b * N + tid] = s;
    }
}

extern "C" void kernel_launch(void* const* d_in, const int* in_sizes, int n_in,
                              void* d_out, int out_size) {
    const int*   ids   = (const int*)d_in[0];
    const int*   lens  = (const int*)d_in[1];
    const float* h0    = (const float*)d_in[2];
    const float* c0    = (const float*)d_in[3];
    const float* emb   = (const float*)d_in[4];
    const float* Wihf  = (const float*)d_in[5];
    const float* Whhf  = (const float*)d_in[6];
    const float* Wihb  = (const float*)d_in[7];
    const float* Whhb  = (const float*)d_in[8];
    const float* S1    = (const float*)d_in[9];
    const float* S2    = (const float*)d_in[10];
    const float* Wet   = (const float*)d_in[11];
    const float* bet   = (const float*)d_in[12];
    const float* Wdet  = (const float*)d_in[13];
    const float* bdet  = (const float*)d_in[14];
    const float* Wprt  = (const float*)d_in[15];
    const float* bprt  = (const float*)d_in[16];
    const float* Wdprt = (const float*)d_in[17];
    const float* bdprt = (const float*)d_in[18];
    const float* Wpop  = (const float*)d_in[19];
    const float* bpop  = (const float*)d_in[20];
    const float* Wdpop = (const float*)d_in[21];
    const float* bdpop = (const float*)d_in[22];
    float* dout = (float*)d_out;

    static int smem_set = 0;
    if (!smem_set) {
        cudaFuncSetAttribute(k_lstm, cudaFuncAttributeMaxDynamicSharedMemorySize,
                             LSTM_SMEM_FLOATS * 4);
        smem_set = 1;
    }

    k_transpose<<<dim3(16, 2), dim3(32, 8)>>>(S1);
    k_gemm_xw<<<dim3(8, 512, 2), 256>>>(ids, emb, Wihf, Wihb, lens);
    k_lstm<<<dim3(64, 2), 512, LSTM_SMEM_FLOATS * 4>>>(Whhf, Whhb, h0, c0, lens, dout);
    k_s2<<<4096, 256>>>(S2, lens);
    k_softmax<<<dim3(Rr, Bb), 256>>>(lens, dout);
    k_M<<<Bb, 512>>>(lens, dout);
    k_aat<<<Bb, 256>>>(lens, dout);
    k_pen<<<1, 64>>>(dout);
    k_hid<<<96, 256>>>(Wet, bet, Wprt, bprt, Wpop, bpop);
    k_dec<<<dim3(Bb, 3), 64>>>(Wdet, bdet, Wdprt, bdprt, Wdpop, bdpop, dout);
}

// round 14
// speedup vs baseline: 1.2971x; 1.1254x over previous
#include <cuda_runtime.h>
#include <math.h>
#include <stdint.h>

#define Bb 64
#define Ss 1024
#define Ee 300
#define Hh 256
#define Gg 1024
#define DHh 512
#define DAa 64
#define Rr 16
#define MHh 512
#define RKk 8192

#define ET_OFF   0
#define PRT_OFF  3200
#define POPT_OFF 3968
#define H_OFF    4480
#define C_OFF    37248
#define PEN_OFF  70016
#define A_OFF    70017

__device__ float g_xw_f[Bb * Ss * Gg];
__device__ float g_xw_b[Bb * Ss * Gg];
__device__ float g_S1t[DHh * DAa];
__device__ float g_Hout[Bb * Ss * DHh];
__device__ float g_s2[Bb * Rr * Ss];   // [b][r][t]
__device__ float g_BM[Bb * RKk];
__device__ float g_hid[3 * Bb * MHh];
__device__ float g_pp[Bb];

__device__ __forceinline__ float sigf(float x) {
    return 1.f / (1.f + expf(-x));
}
__device__ __forceinline__ float fsig(float x) {
    return __fdividef(1.f, 1.f + __expf(-x));
}
__device__ __forceinline__ float ftanh(float x) {
    return 1.f - __fdividef(2.f, __expf(2.f * x) + 1.f);
}
__device__ __forceinline__ void ffma2(unsigned long long& d, unsigned long long a,
                                      unsigned long long b) {
    asm("fma.rn.f32x2 %0, %1, %2, %0;" : "+l"(d) : "l"(a), "l"(b));
}
__device__ __forceinline__ unsigned long long pack2(float x, float y) {
    unsigned long long r;
    asm("mov.b64 %0, {%1, %2};" : "=l"(r) : "r"(__float_as_uint(x)), "r"(__float_as_uint(y)));
    return r;
}
__device__ __forceinline__ float hadd2(unsigned long long v) {
    union { unsigned long long u; float2 f; } cv;
    cv.u = v;
    return cv.f.x + cv.f.y;
}
__device__ __forceinline__ uint32_t smem_u32(const void* p) {
    return (uint32_t)__cvta_generic_to_shared(p);
}
__device__ __forceinline__ uint32_t mapa_u32(uint32_t a, uint32_t r) {
    uint32_t o;
    asm("mapa.shared::cluster.u32 %0, %1, %2;" : "=r"(o) : "r"(a), "r"(r));
    return o;
}
__device__ __forceinline__ void stc_f32(uint32_t a, float v) {
    asm volatile("st.shared::cluster.f32 [%0], %1;" :: "r"(a), "f"(v) : "memory");
}
__device__ __forceinline__ void mbar_init(uint32_t a, uint32_t cnt) {
    asm volatile("mbarrier.init.shared.b64 [%0], %1;" :: "r"(a), "r"(cnt) : "memory");
}
__device__ __forceinline__ void mbar_arrive_peer(uint32_t local_addr, uint32_t rank) {
    asm volatile(
        "{\n\t.reg .b32 ra;\n\t"
        "mapa.shared::cluster.u32 ra, %0, %1;\n\t"
        "mbarrier.arrive.shared::cluster.b64 _, [ra];\n\t}"
        :: "r"(local_addr), "r"(rank) : "memory");
}
__device__ __forceinline__ void mbar_waitc(uint32_t addr, uint32_t parity) {
    uint32_t done;
    do {
        asm volatile(
            "{\n\t.reg .pred p;\n\t"
            "mbarrier.try_wait.parity.acquire.cluster.shared::cta.b64 p, [%1], %2;\n\t"
            "selp.b32 %0, 1, 0, p;\n\t}"
            : "=r"(done) : "r"(addr), "r"(parity) : "memory");
    } while (!done);
}
#define FENCE_CLUSTER() asm volatile("fence.acq_rel.cluster;" ::: "memory")
#define GROUP_BAR(id) asm volatile("bar.sync %0, %1;" :: "r"(id), "r"(256) : "memory")
#define CLUSTER_SYNC() do { \
    asm volatile("barrier.cluster.arrive.aligned;" ::: "memory"); \
    asm volatile("barrier.cluster.wait.aligned;" ::: "memory"); \
} while (0)

// ---- S1 transpose only (64x512 -> 512x64)
__global__ void k_transpose(const float* __restrict__ S1) {
    int c0 = blockIdx.x * 32, r0 = blockIdx.y * 32;
    __shared__ float tile[32][33];
    int tx = threadIdx.x, ty = threadIdx.y;
#pragma unroll
    for (int i = 0; i < 4; i++)
        tile[ty + i * 8][tx] = S1[(size_t)(r0 + ty + i * 8) * DHh + c0 + tx];
    __syncthreads();
#pragma unroll
    for (int i = 0; i < 4; i++)
        g_S1t[(size_t)(c0 + ty + i * 8) * DAa + r0 + tx] = tile[tx][ty + i * 8];
}

// ---- xw = emb[ids] @ W_ih^T (M=65536, N=1024, K=300), both dirs; skip masked tiles
__global__ void __launch_bounds__(256) k_gemm_xw(const int* __restrict__ ids,
                                                 const float* __restrict__ emb,
                                                 const float* __restrict__ Wf,
                                                 const float* __restrict__ Wb,
                                                 const int* __restrict__ len_li) {
    int m0 = blockIdx.y * 128, n0 = blockIdx.x * 128;
    {
        int b = m0 >> 10, t0 = m0 & 1023;
        if (t0 >= len_li[b]) return;
    }
    const float* Wp = blockIdx.z ? Wb : Wf;
    float* out = blockIdx.z ? g_xw_b : g_xw_f;
    __shared__ __align__(16) float As[8][128];
    __shared__ __align__(16) float Bs[8][128];
    __shared__ int roff[128];
    int tid = threadIdx.x;
    if (tid < 128) roff[tid] = ids[m0 + tid] * Ee;

    unsigned long long acc2[8][4];
#pragma unroll
    for (int i = 0; i < 8; i++)
#pragma unroll
        for (int j = 0; j < 4; j++) acc2[i][j] = 0ULL;

    int mloc = tid >> 1;
    int kloc = (tid & 1) * 4;
    int ty = tid >> 4, tx = tid & 15;
    __syncthreads();

    for (int k0 = 0; k0 < Ee; k0 += 8) {
#pragma unroll
        for (int i = 0; i < 4; i++) {
            int kk = kloc + i, kg = k0 + kk;
            As[kk][mloc] = (kg < Ee) ? emb[(size_t)roff[mloc] + kg] : 0.f;
            Bs[kk][mloc] = (kg < Ee) ? Wp[(size_t)(n0 + mloc) * Ee + kg] : 0.f;
        }
        __syncthreads();
#pragma unroll
        for (int kk = 0; kk < 8; kk++) {
            float a[8];
            *(float4*)&a[0] = *(float4*)&As[kk][ty * 8];
            *(float4*)&a[4] = *(float4*)&As[kk][ty * 8 + 4];
            unsigned long long bp[4];
            const unsigned long long* bsrc = (const unsigned long long*)&Bs[kk][tx * 8];
            bp[0] = bsrc[0]; bp[1] = bsrc[1]; bp[2] = bsrc[2]; bp[3] = bsrc[3];
#pragma unroll
            for (int i = 0; i < 8; i++) {
                unsigned long long ad = pack2(a[i], a[i]);
                ffma2(acc2[i][0], ad, bp[0]);
                ffma2(acc2[i][1], ad, bp[1]);
                ffma2(acc2[i][2], ad, bp[2]);
                ffma2(acc2[i][3], ad, bp[3]);
            }
        }
        __syncthreads();
    }
#pragma unroll
    for (int i = 0; i < 8; i++) {
        float* orow = out + (size_t)(m0 + ty * 8 + i) * Gg + n0 + tx * 8;
        ((ulonglong2*)orow)[0] = make_ulonglong2(acc2[i][0], acc2[i][1]);
        ((ulonglong2*)orow)[1] = make_ulonglong2(acc2[i][2], acc2[i][3]);
    }
}

// ---- LSTM recurrence: cluster of 8 CTAs per 8 batches, W slice in smem,
// TWO pipelined groups of 4 batches with per-group mbarrier h-exchange.
// grid (64, 2), cluster (8,1,1), 512 threads.
// smem floats: Wv 32768 | hb [2 grp][2 buf][4 m][256 j] = 4096 | sg 2*128*17 = 4352
#define LSTM_SMEM_FLOATS (32768 + 4096 + 4352)
__global__ void __launch_bounds__(512, 1) __cluster_dims__(8, 1, 1)
k_lstm(const float* __restrict__ Whf, const float* __restrict__ Whb,
       const float* __restrict__ h0, const float* __restrict__ c0,
       const int* __restrict__ len_li, float* __restrict__ dout) {
    extern __shared__ float smem[];
    float4* Wv = (float4*)smem;                    // [pp(64)][cc(128)]
    float* hb = smem + 32768;                      // [g*2048 + buf*1024 + m*256 + j]
    float* sgb = smem + 32768 + 4096;              // per group 128*17
    __shared__ int slen[8];
    __shared__ __align__(8) unsigned long long mbar[4];   // [g*2 + buf]

    int tid = threadIdx.x;
    int dir = blockIdx.y;
    int rank = blockIdx.x & 7;
    int b0 = (blockIdx.x >> 3) * 8;
    int j0 = rank * 32;
    const float* Whh = dir ? Whb : Whf;
    const float* xw  = dir ? g_xw_b : g_xw_f;

    // load W rows for this CTA's 128 gate columns
    for (int i = tid; i < 128 * 64; i += 512) {
        int cc = i >> 6, pp = i & 63;
        int gcol = (cc >> 5) * 256 + j0 + (cc & 31);
        Wv[pp * 128 + cc] = *(const float4*)&Whh[(size_t)gcol * Hh + pp * 4];
    }
    // load h0 (8 batches) into buffer 0 of each group
    for (int i = tid; i < 8 * Hh; i += 512) {
        int m = i >> 8, j = i & 255;      // m 0..7
        int g = m >> 2, ml = m & 3;
        hb[g * 2048 + ml * 256 + j] = h0[(size_t)(dir * Bb + b0 + m) * Hh + j];
    }
    if (tid < 8) slen[tid] = len_li[b0 + tid];
    if (tid < 4) mbar_init(smem_u32(&mbar[tid]), 8);
    __syncthreads();
    CLUSTER_SYNC();

    // ---- group decomposition
    int g = tid >> 8;                 // 0 or 1
    int tg = tid & 255;               // tid within group
    int barid = 1 + g;
    float* sg = sgb + g * 2176;
    float* hbg = hb + g * 2048;
    int mlen = max(max(slen[g * 4], slen[g * 4 + 1]),
                   max(slen[g * 4 + 2], slen[g * 4 + 3]));

    // phase-A mapping: cs 0..63 (cols {cs, cs+64}), ks 0..3 (16 float4 k-chunks)
    int cs = tg & 63;
    int ks = tg >> 6;
    int col0 = cs, col1 = cs + 64;
    int ppbase = ks * 16;
    int gcol0 = (col0 >> 5) * 256 + j0 + (col0 & 31);
    int gcol1 = (col1 >> 5) * 256 + j0 + (col1 & 31);
    int lenx = slen[g * 4 + ks];      // xv owner batch = ks
    const float* xw0 = xw + ((size_t)(b0 + g * 4 + ks) * Ss) * Gg + gcol0;
    const float* xw1 = xw + ((size_t)(b0 + g * 4 + ks) * Ss) * Gg + gcol1;
    const ulonglong2* Wu = (const ulonglong2*)Wv;

    // phase-B mapping: first 128 group threads -> (batch pb 0..3, dim pj 0..31)
    bool bact = tg < 128;
    int pb = (tg >> 5) & 3, pj = tg & 31;
    int plen = slen[g * 4 + pb];
    float creg = bact ? c0[(size_t)(dir * Bb + b0 + g * 4 + pb) * Hh + j0 + pj] : 0.f;
    float hreg = bact ? hbg[pb * 256 + j0 + pj] : 0.f;

    uint32_t hb_u = smem_u32(hb);
    uint32_t peer[8];
#pragma unroll
    for (int r = 0; r < 8; r++) peer[r] = mapa_u32(hb_u, (uint32_t)r);

    int cur = 0;
    int ph0 = 0, ph1 = 0;
    for (int t = 0; t < mlen; t++) {
        if (t > 0) {
            if (cur == 0) { mbar_waitc(smem_u32(&mbar[g * 2 + 0]), ph0); ph0 ^= 1; }
            else          { mbar_waitc(smem_u32(&mbar[g * 2 + 1]), ph1); ph1 ^= 1; }
        }
        // xv for owned batch
        int pos = dir ? lenx - 1 - t : t;
        if (pos < 0) pos = 0;
        float xv0 = __ldg(xw0 + (size_t)pos * Gg);
        float xv1 = __ldg(xw1 + (size_t)pos * Gg);

        // dot: 2 cols x 4 batches over this thread's 64 k values
        unsigned long long acc[2][4] = {{0ULL,0ULL,0ULL,0ULL},{0ULL,0ULL,0ULL,0ULL}};
        const float* hc = hbg + cur * 1024;
#pragma unroll 8
        for (int pp = 0; pp < 16; pp++) {
            ulonglong2 w0 = Wu[(ppbase + pp) * 128 + col0];
            ulonglong2 w1 = Wu[(ppbase + pp) * 128 + col1];
#pragma unroll
            for (int m = 0; m < 4; m++) {
                ulonglong2 hv = *(const ulonglong2*)&hc[m * 256 + (ppbase + pp) * 4];
                ffma2(acc[0][m], w0.x, hv.x); ffma2(acc[0][m], w0.y, hv.y);
                ffma2(acc[1][m], w1.x, hv.x); ffma2(acc[1][m], w1.y, hv.y);
            }
        }
#pragma unroll
        for (int m = 0; m < 4; m++) {
            float p0 = hadd2(acc[0][m]);
            float p1 = hadd2(acc[1][m]);
            if (m == ks) { p0 += xv0; p1 += xv1; }
            sg[col0 * 17 + ks * 4 + m] = p0;
            sg[col1 * 17 + ks * 4 + m] = p1;
        }
        GROUP_BAR(barid);

        int nxt = cur ^ 1;
        if (bact) {
            int bi = pj * 17 + pb;
            float gi = sg[bi] + sg[bi + 4] + sg[bi + 8] + sg[bi + 12];
            bi = (32 + pj) * 17 + pb;
            float gf = sg[bi] + sg[bi + 4] + sg[bi + 8] + sg[bi + 12];
            bi = (64 + pj) * 17 + pb;
            float gg = sg[bi] + sg[bi + 4] + sg[bi + 8] + sg[bi + 12];
            bi = (96 + pj) * 17 + pb;
            float go = sg[bi] + sg[bi + 4] + sg[bi + 8] + sg[bi + 12];
            if (t < plen) {
                creg = fsig(gf) * creg + fsig(gi) * ftanh(gg);
                hreg = fsig(go) * ftanh(creg);
                int posw = dir ? plen - 1 - t : t;
                g_Hout[((size_t)(b0 + g * 4 + pb) * Ss + posw) * DHh + dir * Hh + j0 + pj] = hreg;
            }
            if (t + 1 < mlen) {
                uint32_t off = (uint32_t)((g * 2048 + nxt * 1024 + pb * 256 + j0 + pj) * 4);
#pragma unroll
                for (int r = 0; r < 8; r++) stc_f32(peer[r] + off, hreg);
            }
        }
        GROUP_BAR(barid);
        if (t + 1 < mlen && tg < 8) {
            FENCE_CLUSTER();
            mbar_arrive_peer(smem_u32(&mbar[g * 2 + nxt]), (uint32_t)tg);
        }
        cur = nxt;
    }
    if (bact) {
        dout[H_OFF + (size_t)(dir * Bb + b0 + g * 4 + pb) * Hh + j0 + pj] = hreg;
        dout[C_OFF + (size_t)(dir * Bb + b0 + g * 4 + pb) * Hh + j0 + pj] = creg;
    }
    CLUSTER_SYNC();
}

// ---- s2 = tanh(Hout @ S1^T) @ S2^T, write [b][r][t]; skip masked tiles
__global__ void __launch_bounds__(256) k_s2(const float* __restrict__ S2,
                                            const int* __restrict__ len_li) {
    size_t row0 = (size_t)blockIdx.x * 16;
    int b = (int)(row0 >> 10);
    int t0 = (int)(row0 & 1023);
    if (t0 >= len_li[b]) return;

    __shared__ __align__(16) float Hs[16][DHh];
    __shared__ float t1[16][DAa];
    __shared__ float so[16][17];
    int tid = threadIdx.x;
    for (int idx = tid; idx < 16 * DHh / 4; idx += 256) {
        int r = idx / (DHh / 4);
        int c4 = (idx % (DHh / 4)) * 4;
        *(float4*)&Hs[r][c4] = *(const float4*)&g_Hout[(row0 + r) * DHh + c4];
    }
    __syncthreads();

    int da = tid & 63;
    int rl = tid >> 6;
    float acc[4] = {0.f, 0.f, 0.f, 0.f};
    for (int k = 0; k < DHh; k++) {
        float w = g_S1t[(size_t)k * DAa + da];
        acc[0] = fmaf(w, Hs[rl + 0][k], acc[0]);
        acc[1] = fmaf(w, Hs[rl + 4][k], acc[1]);
        acc[2] = fmaf(w, Hs[rl + 8][k], acc[2]);
        acc[3] = fmaf(w, Hs[rl + 12][k], acc[3]);
    }
    t1[rl + 0][da]  = tanhf(acc[0]);
    t1[rl + 4][da]  = tanhf(acc[1]);
    t1[rl + 8][da]  = tanhf(acc[2]);
    t1[rl + 12][da] = tanhf(acc[3]);
    __syncthreads();

    int row = tid >> 4, rh = tid & 15;
    float s = 0.f;
#pragma unroll 8
    for (int k = 0; k < DAa; k++) s = fmaf(t1[row][k], __ldg(&S2[rh * DAa + k]), s);
    so[row][rh] = s;
    __syncthreads();
    int rr = tid >> 4, tt = tid & 15;
    g_s2[((size_t)b * Rr + rr) * Ss + t0 + tt] = so[tt][rr];
}

// ---- masked softmax over t; A written to dout. grid (R, B)
__global__ void __launch_bounds__(256) k_softmax(const int* __restrict__ len_li,
                                                 float* __restrict__ dout) {
    int r = blockIdx.x, b = blockIdx.y;
    int len = len_li[b];
    int tid = threadIdx.x;
    __shared__ float red[256];
    const float* srow = g_s2 + ((size_t)b * Rr + r) * Ss;
    float* Aout = dout + A_OFF + ((size_t)b * Rr + r) * Ss;

    float m = -1e30f;
    for (int t = tid; t < len; t += 256) m = fmaxf(m, srow[t]);
    red[tid] = m; __syncthreads();
    for (int s = 128; s > 0; s >>= 1) {
        if (tid < s) red[tid] = fmaxf(red[tid], red[tid + s]);
        __syncthreads();
    }
    float M = red[0]; __syncthreads();

    float sum = 0.f;
    for (int t = tid; t < len; t += 256) {
        float e = expf(srow[t] - M);
        Aout[t] = e;
        sum += e;
    }
    red[tid] = sum; __syncthreads();
    for (int s = 128; s > 0; s >>= 1) {
        if (tid < s) red[tid] += red[tid + s];
        __syncthreads();
    }
    float inv = 1.f / red[0];

    for (int t = tid; t < Ss; t += 256)
        Aout[t] = (t < len) ? Aout[t] * inv : 0.f;
}

// ---- BM = A @ Hout. block per b, 512 thr (d)
__global__ void __launch_bounds__(512) k_M(const int* __restrict__ len_li,
                                           const float* __restrict__ dout) {
    int b = blockIdx.x;
    int tid = threadIdx.x;
    int len = len_li[b];
    __shared__ __align__(16) float Asm[128][16];
    float acc[16];
#pragma unroll
    for (int i = 0; i < 16; i++) acc[i] = 0.f;

    const float* Abase = dout + A_OFF + (size_t)b * Rr * Ss;
    for (int tc = 0; tc < len; tc += 128) {
        int nt = min(128, len - tc);
        for (int idx = tid; idx < 16 * 128; idx += 512) {
            int r = idx >> 7, tt = idx & 127;
            Asm[tt][r] = (tt < nt) ? Abase[(size_t)r * Ss + tc + tt] : 0.f;
        }
        __syncthreads();
        for (int tt = 0; tt < nt; tt++) {
            float hv = g_Hout[((size_t)b * Ss + tc + tt) * DHh + tid];
#pragma unroll
            for (int r2 = 0; r2 < 16; r2++)
                acc[r2] = fmaf(Asm[tt][r2], hv, acc[r2]);
        }
        __syncthreads();
    }
#pragma unroll
    for (int r2 = 0; r2 < 16; r2++)
        g_BM[(size_t)b * RKk + r2 * DHh + tid] = acc[r2];
}

// ---- AAT penal partial. block per b, thread (r,q)
__global__ void __launch_bounds__(256) k_aat(const int* __restrict__ len_li,
                                             const float* __restrict__ dout) {
    int b = blockIdx.x;
    int tid = threadIdx.x;
    int r = tid >> 4, q = tid & 15;
    int len = len_li[b];
    const float* Abase = dout + A_OFF + (size_t)b * Rr * Ss;
    __shared__ float As2[16][257];
    float s = 0.f;
    for (int tc = 0; tc < len; tc += 256) {
        int nt = min(256, len - tc);
        for (int i = tid; i < 16 * 256; i += 256) {
            int rr = i >> 8, tt = i & 255;
            As2[rr][tt] = (tt < nt) ? Abase[(size_t)rr * Ss + tc + tt] : 0.f;
        }
        __syncthreads();
#pragma unroll 4
        for (int tt = 0; tt < 256; tt++)
            s = fmaf(As2[r][tt], As2[q][tt], s);
        __syncthreads();
    }
    float d = s - (r == q ? 1.f : 0.f);
    __shared__ float red[256];
    red[tid] = d * d; __syncthreads();
    for (int st = 128; st > 0; st >>= 1) {
        if (tid < st) red[tid] += red[tid + st];
        __syncthreads();
    }
    if (tid == 0) g_pp[b] = red[0];
}

__global__ void k_pen(float* __restrict__ dout) {
    __shared__ float red[64];
    int tid = threadIdx.x;
    red[tid] = g_pp[tid]; __syncthreads();
    for (int st = 32; st > 0; st >>= 1) {
        if (tid < st) red[tid] += red[tid + st];
        __syncthreads();
    }
    if (tid == 0) dout[PEN_OFF] = red[0] / 64.f;
}

// ---- hid = relu(BM @ W^T + b): tiled GEMM, 96 blocks
__global__ void __launch_bounds__(256) k_hid(const float* __restrict__ Wet,  const float* __restrict__ bet,
                                             const float* __restrict__ Wprt, const float* __restrict__ bprt,
                                             const float* __restrict__ Wpop, const float* __restrict__ bpop) {
    int blk = blockIdx.x;
    int head = blk >> 5;
    int j0 = (blk & 31) * 16;
    const float* W    = (head == 0) ? Wet : (head == 1) ? Wprt : Wpop;
    const float* bias = (head == 0) ? bet : (head == 1) ? bprt : bpop;
    __shared__ float Ws[16][64];
    __shared__ float Bs[64][65];
    int tid = threadIdx.x;
    int rj = tid >> 4;
    int bq = (tid & 15) * 4;
    float acc[4] = {0.f, 0.f, 0.f, 0.f};
    for (int kc = 0; kc < RKk; kc += 64) {
        for (int i = tid; i < 1024; i += 256) {
            int r = i >> 6, k = i & 63;
            Ws[r][k] = W[(size_t)(j0 + r) * RKk + kc + k];
        }
        for (int i = tid; i < 4096; i += 256) {
            int bx = i >> 6, k = i & 63;
            Bs[bx][k] = g_BM[(size_t)bx * RKk + kc + k];
        }
        __syncthreads();
#pragma unroll 4
        for (int k = 0; k < 64; k++) {
            float w = Ws[rj][k];
            acc[0] = fmaf(w, Bs[bq + 0][k], acc[0]);
            acc[1] = fmaf(w, Bs[bq + 1][k], acc[1]);
            acc[2] = fmaf(w, Bs[bq + 2][k], acc[2]);
            acc[3] = fmaf(w, Bs[bq + 3][k], acc[3]);
        }
        __syncthreads();
    }
    float bv = bias[j0 + rj];
#pragma unroll
    for (int q = 0; q < 4; q++)
        g_hid[((size_t)head * Bb + bq + q) * MHh + j0 + rj] = fmaxf(acc[q] + bv, 0.f);
}

// ---- decode: grid (B, 3), 64 threads
__global__ void __launch_bounds__(64) k_dec(const float* __restrict__ Wdet,  const float* __restrict__ bdet,
                                            const float* __restrict__ Wdprt, const float* __restrict__ bdprt,
                                            const float* __restrict__ Wdpop, const float* __restrict__ bdpop,
                                            float* __restrict__ dout) {
    int b = blockIdx.x, head = blockIdx.y;
    int tid = threadIdx.x;
    const float* Wd; const float* bd; int N; int off;
    if (head == 0)      { Wd = Wdet;  bd = bdet;  N = 50; off = ET_OFF;   }
    else if (head == 1) { Wd = Wdprt; bd = bdprt; N = 12; off = PRT_OFF;  }
    else                { Wd = Wdpop; bd = bdpop; N = 8;  off = POPT_OFF; }
    __shared__ float sh[MHh];
    for (int k = tid; k < MHh; k += 64)
        sh[k] = g_hid[((size_t)head * Bb + b) * MHh + k];
    __syncthreads();
    if (tid < N) {
        float s = bd[tid];
        const float* wr = Wd + (size_t)tid * MHh;
        for (int k = 0; k < MHh; k++) s = fmaf(sh[k], wr[k], s);
        dout[off + b * N + tid] = s;
    }
}

extern "C" void kernel_launch(void* const* d_in, const int* in_sizes, int n_in,
                              void* d_out, int out_size) {
    const int*   ids   = (const int*)d_in[0];
    const int*   lens  = (const int*)d_in[1];
    const float* h0    = (const float*)d_in[2];
    const float* c0    = (const float*)d_in[3];
    const float* emb   = (const float*)d_in[4];
    const float* Wihf  = (const float*)d_in[5];
    const float* Whhf  = (const float*)d_in[6];
    const float* Wihb  = (const float*)d_in[7];
    const float* Whhb  = (const float*)d_in[8];
    const float* S1    = (const float*)d_in[9];
    const float* S2    = (const float*)d_in[10];
    const float* Wet   = (const float*)d_in[11];
    const float* bet   = (const float*)d_in[12];
    const float* Wdet  = (const float*)d_in[13];
    const float* bdet  = (const float*)d_in[14];
    const float* Wprt  = (const float*)d_in[15];
    const float* bprt  = (const float*)d_in[16];
    const float* Wdprt = (const float*)d_in[17];
    const float* bdprt = (const float*)d_in[18];
    const float* Wpop  = (const float*)d_in[19];
    const float* bpop  = (const float*)d_in[20];
    const float* Wdpop = (const float*)d_in[21];
    const float* bdpop = (const float*)d_in[22];
    float* dout = (float*)d_out;

    static int smem_set = 0;
    if (!smem_set) {
        cudaFuncSetAttribute(k_lstm, cudaFuncAttributeMaxDynamicSharedMemorySize,
                             LSTM_SMEM_FLOATS * 4);
        smem_set = 1;
    }

    k_transpose<<<dim3(16, 2), dim3(32, 8)>>>(S1);
    k_gemm_xw<<<dim3(8, 512, 2), 256>>>(ids, emb, Wihf, Wihb, lens);
    k_lstm<<<dim3(64, 2), 512, LSTM_SMEM_FLOATS * 4>>>(Whhf, Whhb, h0, c0, lens, dout);
    k_s2<<<4096, 256>>>(S2, lens);
    k_softmax<<<dim3(Rr, Bb), 256>>>(lens, dout);
    k_M<<<Bb, 512>>>(lens, dout);
    k_aat<<<Bb, 256>>>(lens, dout);
    k_pen<<<1, 64>>>(dout);
    k_hid<<<96, 256>>>(Wet, bet, Wprt, bprt, Wpop, bpop);
    k_dec<<<dim3(Bb, 3), 64>>>(Wdet, bdet, Wdprt, bdprt, Wdpop, bdpop, dout);
}